// round 11
// baseline (speedup 1.0000x reference)
#include <cuda_runtime.h>
#include <cstdint>

// MyLoss: fused log_softmax CE -> per-batch sigmoid-CE-style loss.
// SINGLE kernel, one row per block (max resident occupancy; drains hidden by
// 8 co-resident CTAs/SM), shuffle-based block reduction, per-batch float
// atomic accumulation, last-block finalization via release/acquire atomics.
// At 6322 GB/s this kernel sits on the B300 LTS throughput cap (~6300 B/cyc,
// path-independent) -- the hardware floor for streaming 822 MB is ~130 us.
// Inputs (metadata order): outputs f32 [B,T,V], targets i32 [B,L],
// ratings i32 [B], stage i32 [1] (may be absent -> thresh=4).
// Output: 1x f32 scalar.

#define NTHREADS 256
#define SKIP_TOK 15   // MAX_TOPIC_LEN + SEQ_LEN
#define MAXB 64

__device__ float        g_batch_sum[MAXB];   // zero at module load; reset by last block
__device__ unsigned int g_done;              // ditto

// Mean-zero Schraudolph exp:
//   exp(x) ~= __int_as_float(round(a*x + b)),  a = 2^23/ln2 = 12102203.1616
//   b = 127*2^23 - round(gamma*2^23), gamma = log2(Int_0^1 (1+phi) 2^-phi dphi) = 0.0575313
// Magic-add form (avoids F2I): z = fma(x, a/256, C); bits = bits(z)<<8
#define AEXP_K 47274.2311f
#define AEXP_C 12548258.8f

__device__ __forceinline__ float aexp(float v) {
    float z = __fmaf_rn(v, AEXP_K, AEXP_C);
    return __int_as_float(__float_as_int(z) << 8);
}

// min 8 blocks/SM => <=32 regs => 2048 threads resident => max MLP at the LSU
__global__ __launch_bounds__(NTHREADS, 8) void fused_loss_kernel(
    const float* __restrict__ outputs,
    const int* __restrict__ targets,
    const int* __restrict__ ratings,
    const int* __restrict__ stage,
    float* __restrict__ out,
    int T, int V, int L, int B)
{
    const int row = blockIdx.x;
    const int Lm1 = L - 1;
    const int b = row / Lm1;
    const int t = row - b * Lm1;
    const float* __restrict__ x = outputs + (size_t)(b * T + SKIP_TOK + t) * (size_t)V;

    const int tid  = threadIdx.x;
    const int wid  = tid >> 5;
    const int lane = tid & 31;

    __shared__ float warp_part[NTHREADS / 32];

    float accs = 0.0f;

    // peel to 16B alignment (row stride V=50257 floats is odd)
    int pre = ((16 - ((int)((uintptr_t)x & 15))) & 15) >> 2;
    if (pre > V) pre = V;
    if (tid < pre) accs += aexp(x[tid]);

    const int nvec = (V - pre) >> 2;
    const ulonglong2* __restrict__ xv = (const ulonglong2*)(x + pre);

    // packed constants for f32x2
    const unsigned kb = __float_as_uint(AEXP_K);
    const unsigned cb = __float_as_uint(AEXP_C);
    const unsigned long long Kpk = (unsigned long long)kb | ((unsigned long long)kb << 32);
    const unsigned long long Cpk = (unsigned long long)cb | ((unsigned long long)cb << 32);

    unsigned long long acc0 = 0ull, acc1 = 0ull;   // 4 packed fp32 accumulators

    #pragma unroll 4
    for (int i = tid; i < nvec; i += NTHREADS) {
        ulonglong2 v = xv[i];                      // LDG.128, coalesced
        unsigned long long z0, z1;
        asm("fma.rn.f32x2 %0, %1, %2, %3;" : "=l"(z0) : "l"(v.x), "l"(Kpk), "l"(Cpk));
        asm("fma.rn.f32x2 %0, %1, %2, %3;" : "=l"(z1) : "l"(v.y), "l"(Kpk), "l"(Cpk));
        // 64-bit shift: per-lane <<8; cross-lane contamination only touches the
        // low 8 mantissa bits of the hi lane (2^-15 relative noise, tolerable)
        z0 <<= 8;
        z1 <<= 8;
        asm("add.rn.f32x2 %0, %0, %1;" : "+l"(acc0) : "l"(z0));
        asm("add.rn.f32x2 %0, %0, %1;" : "+l"(acc1) : "l"(z1));
    }

    // tail
    for (int j = pre + (nvec << 2) + tid; j < V; j += NTHREADS)
        accs += aexp(x[j]);

    float s = accs
            + __uint_as_float((unsigned)acc0) + __uint_as_float((unsigned)(acc0 >> 32))
            + __uint_as_float((unsigned)acc1) + __uint_as_float((unsigned)(acc1 >> 32));

    // warp shuffle reduce -> 8 partials -> warp 0 finishes (2 syncs total)
    #pragma unroll
    for (int o = 16; o > 0; o >>= 1)
        s += __shfl_down_sync(0xffffffffu, s, o);
    if (lane == 0) warp_part[wid] = s;
    __syncthreads();

    if (wid == 0) {
        float v = (lane < NTHREADS / 32) ? warp_part[lane] : 0.0f;
        #pragma unroll
        for (int o = 4; o > 0; o >>= 1)
            v += __shfl_down_sync(0xffffffffu, v, o);

        if (lane == 0) {
            int lbl = targets[b * L + (t + 1)];
            if (lbl < 0) lbl = 0;
            if (lbl >= V) lbl = V - 1;
            float lval = __ldg(&x[lbl]);
            float nll = logf(v) - lval;            // tok_nll = lse - logit[label]

            // relaxed device-scope float accumulation into the per-batch sum
            atomicAdd(&g_batch_sum[b], nll);

            // release-increment of the done counter: orders the sum-add above
            // before any observer that acquires.  No MEMBAR / L1D flush.
            unsigned int done;
            asm volatile("atom.add.release.gpu.u32 %0, [%1], %2;"
                         : "=r"(done) : "l"(&g_done), "r"(1u) : "memory");

            if (done == gridDim.x - 1) {
                // last block: acquire-load sums (pairs with release above)
                int thresh = 4;
                if (stage != nullptr) thresh = (stage[0] == 1) ? 4 : 3;
                float tot = 0.0f;
                for (int i = 0; i < B; i++) {
                    float si;
                    asm volatile("ld.acquire.gpu.f32 %0, [%1];"
                                 : "=f"(si) : "l"(&g_batch_sum[i]) : "memory");
                    float ce = si / (float)Lm1;
                    float y  = (ratings[i] > thresh) ? 1.0f : 0.0f;
                    float p  = __expf(-ce);
                    tot += -y * __logf(p + 1e-10f)
                           - (1.0f - y) * __logf(1.0f - p + 1e-10f);
                    g_batch_sum[i] = 0.0f;         // reset for next graph replay
                }
                out[0] = tot / (float)B;
                g_done = 0u;                       // reset counter (kernel-exit
                                                   // boundary publishes it)
            }
        }
    }
}

extern "C" void kernel_launch(void* const* d_in, const int* in_sizes, int n_in,
                              void* d_out, int out_size) {
    const float* outputs = (const float*)d_in[0];
    const int*   targets = (const int*)d_in[1];
    const int*   ratings = (const int*)d_in[2];
    const int*   stage   = (n_in >= 4) ? (const int*)d_in[3] : nullptr;

    int B = in_sizes[2];
    int L = in_sizes[1] / B;
    int T = SKIP_TOK + L;
    int V = (int)((long long)in_sizes[0] / ((long long)B * (long long)T));
    int rows = B * (L - 1);

    fused_loss_kernel<<<rows, NTHREADS>>>(outputs, targets, ratings, stage,
                                          (float*)d_out, T, V, L, B);
}

// round 12
// speedup vs baseline: 1.0166x; 1.0166x over previous
#include <cuda_runtime.h>
#include <cstdint>

// MyLoss: fused log_softmax CE -> per-batch sigmoid-CE-style loss.
// SINGLE kernel: per-row LSE+gather, per-batch float atomic accumulation,
// last-block finalization via release/acquire scoped atomics (no threadfence,
// no second launch boundary).
//
// CONVERGED CONFIGURATION (R8): 4088 blocks x 1 row, smem-tree reduction,
// 32 regs / 8 CTAs/SM. Measured 6322 GB/s = the B300 LTS/DRAM streaming
// ceiling (~6300 B/cyc path-independent); 822 MB / 6.3 TB/s = 130.4 us floor,
// measured 130.3 us. Single-wave grids, shuffle reductions, and split-kernel
// variants were all tried and all regressed 1-3%.
//
// Inputs (metadata order): outputs f32 [B,T,V], targets i32 [B,L],
// ratings i32 [B], stage i32 [1] (may be absent -> thresh=4).
// Output: 1x f32 scalar.

#define NTHREADS 256
#define SKIP_TOK 15   // MAX_TOPIC_LEN + SEQ_LEN
#define MAXB 64

__device__ float        g_batch_sum[MAXB];   // zero at module load; reset by last block
__device__ unsigned int g_done;              // ditto

// Mean-zero Schraudolph exp:
//   exp(x) ~= __int_as_float(round(a*x + b)),  a = 2^23/ln2 = 12102203.1616
//   b = 127*2^23 - round(gamma*2^23), gamma = log2(Int_0^1 (1+phi) 2^-phi dphi) = 0.0575313
// Magic-add form (avoids F2I): z = fma(x, a/256, C); bits = bits(z)<<8
#define AEXP_K 47274.2311f
#define AEXP_C 12548258.8f

__device__ __forceinline__ float aexp(float v) {
    float z = __fmaf_rn(v, AEXP_K, AEXP_C);
    return __int_as_float(__float_as_int(z) << 8);
}

// min 8 blocks/SM => <=32 regs => 2048 threads resident => max MLP at the LSU
__global__ __launch_bounds__(NTHREADS, 8) void fused_loss_kernel(
    const float* __restrict__ outputs,
    const int* __restrict__ targets,
    const int* __restrict__ ratings,
    const int* __restrict__ stage,
    float* __restrict__ out,
    int T, int V, int L, int B)
{
    const int row = blockIdx.x;
    const int Lm1 = L - 1;
    const int b = row / Lm1;
    const int t = row - b * Lm1;
    const float* __restrict__ x = outputs + (size_t)(b * T + SKIP_TOK + t) * (size_t)V;

    const int tid = threadIdx.x;

    float accs = 0.0f;

    // peel to 16B alignment (row stride V=50257 floats is odd)
    int pre = ((16 - ((int)((uintptr_t)x & 15))) & 15) >> 2;
    if (pre > V) pre = V;
    if (tid < pre) accs += aexp(x[tid]);

    const int nvec = (V - pre) >> 2;
    const ulonglong2* __restrict__ xv = (const ulonglong2*)(x + pre);

    // packed constants for f32x2
    const unsigned kb = __float_as_uint(AEXP_K);
    const unsigned cb = __float_as_uint(AEXP_C);
    const unsigned long long Kpk = (unsigned long long)kb | ((unsigned long long)kb << 32);
    const unsigned long long Cpk = (unsigned long long)cb | ((unsigned long long)cb << 32);

    unsigned long long acc0 = 0ull, acc1 = 0ull;   // 4 packed fp32 accumulators

    #pragma unroll 4
    for (int i = tid; i < nvec; i += NTHREADS) {
        ulonglong2 v = xv[i];                      // LDG.128, coalesced
        unsigned long long z0, z1;
        asm("fma.rn.f32x2 %0, %1, %2, %3;" : "=l"(z0) : "l"(v.x), "l"(Kpk), "l"(Cpk));
        asm("fma.rn.f32x2 %0, %1, %2, %3;" : "=l"(z1) : "l"(v.y), "l"(Kpk), "l"(Cpk));
        // 64-bit shift: per-lane <<8; cross-lane contamination only touches the
        // low 8 mantissa bits of the hi lane (2^-15 relative noise, tolerable)
        z0 <<= 8;
        z1 <<= 8;
        asm("add.rn.f32x2 %0, %0, %1;" : "+l"(acc0) : "l"(z0));
        asm("add.rn.f32x2 %0, %0, %1;" : "+l"(acc1) : "l"(z1));
    }

    // tail
    for (int j = pre + (nvec << 2) + tid; j < V; j += NTHREADS)
        accs += aexp(x[j]);

    float s = accs
            + __uint_as_float((unsigned)acc0) + __uint_as_float((unsigned)(acc0 >> 32))
            + __uint_as_float((unsigned)acc1) + __uint_as_float((unsigned)(acc1 >> 32));

    __shared__ float red[NTHREADS];
    red[tid] = s;
    __syncthreads();
    #pragma unroll
    for (int off = NTHREADS / 2; off > 32; off >>= 1) {
        if (tid < off) red[tid] += red[tid + off];
        __syncthreads();
    }

    if (tid < 32) {
        float v = red[tid] + red[tid + 32];
        #pragma unroll
        for (int o = 16; o > 0; o >>= 1)
            v += __shfl_down_sync(0xffffffffu, v, o);

        if (tid == 0) {
            int lbl = targets[b * L + (t + 1)];
            if (lbl < 0) lbl = 0;
            if (lbl >= V) lbl = V - 1;
            float lval = __ldg(&x[lbl]);
            float nll = logf(v) - lval;            // tok_nll = lse - logit[label]

            // relaxed device-scope float accumulation into the per-batch sum
            atomicAdd(&g_batch_sum[b], nll);

            // release-increment of the done counter: orders the sum-add above
            // before any observer that acquires.  No MEMBAR / L1D flush.
            unsigned int done;
            asm volatile("atom.add.release.gpu.u32 %0, [%1], %2;"
                         : "=r"(done) : "l"(&g_done), "r"(1u) : "memory");

            if (done == gridDim.x - 1) {
                // last block: acquire-load sums (pairs with release above)
                int thresh = 4;
                if (stage != nullptr) thresh = (stage[0] == 1) ? 4 : 3;
                float tot = 0.0f;
                for (int i = 0; i < B; i++) {
                    float si;
                    asm volatile("ld.acquire.gpu.f32 %0, [%1];"
                                 : "=f"(si) : "l"(&g_batch_sum[i]) : "memory");
                    float ce = si / (float)Lm1;
                    float y  = (ratings[i] > thresh) ? 1.0f : 0.0f;
                    float p  = __expf(-ce);
                    tot += -y * __logf(p + 1e-10f)
                           - (1.0f - y) * __logf(1.0f - p + 1e-10f);
                    g_batch_sum[i] = 0.0f;         // reset for next graph replay
                }
                out[0] = tot / (float)B;
                g_done = 0u;                       // reset counter (kernel-exit
                                                   // boundary publishes it)
            }
        }
    }
}

extern "C" void kernel_launch(void* const* d_in, const int* in_sizes, int n_in,
                              void* d_out, int out_size) {
    const float* outputs = (const float*)d_in[0];
    const int*   targets = (const int*)d_in[1];
    const int*   ratings = (const int*)d_in[2];
    const int*   stage   = (n_in >= 4) ? (const int*)d_in[3] : nullptr;

    int B = in_sizes[2];
    int L = in_sizes[1] / B;
    int T = SKIP_TOK + L;
    int V = (int)((long long)in_sizes[0] / ((long long)B * (long long)T));
    int rows = B * (L - 1);

    fused_loss_kernel<<<rows, NTHREADS>>>(outputs, targets, ratings, stage,
                                          (float*)d_out, T, V, L, B);
}

// round 13
// speedup vs baseline: 1.0286x; 1.0118x over previous
#include <cuda_runtime.h>
#include <cstdint>

// MyLoss: fused log_softmax CE -> per-batch sigmoid-CE-style loss.
// SINGLE kernel: per-row LSE+gather, per-batch float atomic accumulation,
// last-block finalization via release/acquire scoped atomics.
//
// Converged structure (R8/R12): 4088 blocks x 1 row, smem-tree reduction,
// 32 regs / 8 CTAs/SM, ~6.3 TB/s = B300 streaming ceiling (~130 us floor for
// the 822 MB compulsory stream). R13 delta: streaming loads use .cs
// (evict-first) to cut L1/L2 allocation churn on the zero-reuse stream.
//
// Inputs (metadata order): outputs f32 [B,T,V], targets i32 [B,L],
// ratings i32 [B], stage i32 [1] (may be absent -> thresh=4).
// Output: 1x f32 scalar.

#define NTHREADS 256
#define SKIP_TOK 15   // MAX_TOPIC_LEN + SEQ_LEN
#define MAXB 64

__device__ float        g_batch_sum[MAXB];   // zero at module load; reset by last block
__device__ unsigned int g_done;              // ditto

// Mean-zero Schraudolph exp:
//   exp(x) ~= __int_as_float(round(a*x + b)),  a = 2^23/ln2 = 12102203.1616
//   b = 127*2^23 - round(gamma*2^23), gamma = log2(Int_0^1 (1+phi) 2^-phi dphi) = 0.0575313
// Magic-add form (avoids F2I): z = fma(x, a/256, C); bits = bits(z)<<8
#define AEXP_K 47274.2311f
#define AEXP_C 12548258.8f

__device__ __forceinline__ float aexp(float v) {
    float z = __fmaf_rn(v, AEXP_K, AEXP_C);
    return __int_as_float(__float_as_int(z) << 8);
}

// streaming (evict-first) 16B load
__device__ __forceinline__ uint4 ldg_cs_128(const uint4* p) {
    uint4 u;
    asm volatile("ld.global.cs.v4.u32 {%0,%1,%2,%3}, [%4];"
                 : "=r"(u.x), "=r"(u.y), "=r"(u.z), "=r"(u.w) : "l"(p));
    return u;
}

// min 8 blocks/SM => <=32 regs => 2048 threads resident => max MLP at the LSU
__global__ __launch_bounds__(NTHREADS, 8) void fused_loss_kernel(
    const float* __restrict__ outputs,
    const int* __restrict__ targets,
    const int* __restrict__ ratings,
    const int* __restrict__ stage,
    float* __restrict__ out,
    int T, int V, int L, int B)
{
    const int row = blockIdx.x;
    const int Lm1 = L - 1;
    const int b = row / Lm1;
    const int t = row - b * Lm1;
    const float* __restrict__ x = outputs + (size_t)(b * T + SKIP_TOK + t) * (size_t)V;

    const int tid = threadIdx.x;

    float accs = 0.0f;

    // peel to 16B alignment (row stride V=50257 floats is odd)
    int pre = ((16 - ((int)((uintptr_t)x & 15))) & 15) >> 2;
    if (pre > V) pre = V;
    if (tid < pre) accs += aexp(x[tid]);

    const int nvec = (V - pre) >> 2;
    const uint4* __restrict__ xv = (const uint4*)(x + pre);

    // packed constants for f32x2
    const unsigned kb = __float_as_uint(AEXP_K);
    const unsigned cb = __float_as_uint(AEXP_C);
    const unsigned long long Kpk = (unsigned long long)kb | ((unsigned long long)kb << 32);
    const unsigned long long Cpk = (unsigned long long)cb | ((unsigned long long)cb << 32);

    unsigned long long acc0 = 0ull, acc1 = 0ull;   // 4 packed fp32 accumulators

    #pragma unroll 4
    for (int i = tid; i < nvec; i += NTHREADS) {
        uint4 u = ldg_cs_128(xv + i);              // LDG.128.CS, coalesced, evict-first
        unsigned long long vlo = ((unsigned long long)u.y << 32) | u.x;
        unsigned long long vhi = ((unsigned long long)u.w << 32) | u.z;
        unsigned long long z0, z1;
        asm("fma.rn.f32x2 %0, %1, %2, %3;" : "=l"(z0) : "l"(vlo), "l"(Kpk), "l"(Cpk));
        asm("fma.rn.f32x2 %0, %1, %2, %3;" : "=l"(z1) : "l"(vhi), "l"(Kpk), "l"(Cpk));
        // 64-bit shift: per-lane <<8; cross-lane contamination only touches the
        // low 8 mantissa bits of the hi lane (2^-15 relative noise, tolerable)
        z0 <<= 8;
        z1 <<= 8;
        asm("add.rn.f32x2 %0, %0, %1;" : "+l"(acc0) : "l"(z0));
        asm("add.rn.f32x2 %0, %0, %1;" : "+l"(acc1) : "l"(z1));
    }

    // tail
    for (int j = pre + (nvec << 2) + tid; j < V; j += NTHREADS)
        accs += aexp(x[j]);

    float s = accs
            + __uint_as_float((unsigned)acc0) + __uint_as_float((unsigned)(acc0 >> 32))
            + __uint_as_float((unsigned)acc1) + __uint_as_float((unsigned)(acc1 >> 32));

    __shared__ float red[NTHREADS];
    red[tid] = s;
    __syncthreads();
    #pragma unroll
    for (int off = NTHREADS / 2; off > 32; off >>= 1) {
        if (tid < off) red[tid] += red[tid + off];
        __syncthreads();
    }

    if (tid < 32) {
        float v = red[tid] + red[tid + 32];
        #pragma unroll
        for (int o = 16; o > 0; o >>= 1)
            v += __shfl_down_sync(0xffffffffu, v, o);

        if (tid == 0) {
            int lbl = targets[b * L + (t + 1)];
            if (lbl < 0) lbl = 0;
            if (lbl >= V) lbl = V - 1;
            float lval = __ldg(&x[lbl]);
            float nll = logf(v) - lval;            // tok_nll = lse - logit[label]

            // relaxed device-scope float accumulation into the per-batch sum
            atomicAdd(&g_batch_sum[b], nll);

            // release-increment of the done counter: orders the sum-add above
            // before any observer that acquires.  No MEMBAR / L1D flush.
            unsigned int done;
            asm volatile("atom.add.release.gpu.u32 %0, [%1], %2;"
                         : "=r"(done) : "l"(&g_done), "r"(1u) : "memory");

            if (done == gridDim.x - 1) {
                // last block: acquire-load sums (pairs with release above)
                int thresh = 4;
                if (stage != nullptr) thresh = (stage[0] == 1) ? 4 : 3;
                float tot = 0.0f;
                for (int i = 0; i < B; i++) {
                    float si;
                    asm volatile("ld.acquire.gpu.f32 %0, [%1];"
                                 : "=f"(si) : "l"(&g_batch_sum[i]) : "memory");
                    float ce = si / (float)Lm1;
                    float y  = (ratings[i] > thresh) ? 1.0f : 0.0f;
                    float p  = __expf(-ce);
                    tot += -y * __logf(p + 1e-10f)
                           - (1.0f - y) * __logf(1.0f - p + 1e-10f);
                    g_batch_sum[i] = 0.0f;         // reset for next graph replay
                }
                out[0] = tot / (float)B;
                g_done = 0u;                       // reset counter (kernel-exit
                                                   // boundary publishes it)
            }
        }
    }
}

extern "C" void kernel_launch(void* const* d_in, const int* in_sizes, int n_in,
                              void* d_out, int out_size) {
    const float* outputs = (const float*)d_in[0];
    const int*   targets = (const int*)d_in[1];
    const int*   ratings = (const int*)d_in[2];
    const int*   stage   = (n_in >= 4) ? (const int*)d_in[3] : nullptr;

    int B = in_sizes[2];
    int L = in_sizes[1] / B;
    int T = SKIP_TOK + L;
    int V = (int)((long long)in_sizes[0] / ((long long)B * (long long)T));
    int rows = B * (L - 1);

    fused_loss_kernel<<<rows, NTHREADS>>>(outputs, targets, ratings, stage,
                                          (float*)d_out, T, V, L, B);
}